// round 1
// baseline (speedup 1.0000x reference)
#include <cuda_runtime.h>
#include <math.h>

#define NNODES 50000
#define NEDGES 800000

// ---------------- static scratch (no allocations allowed) ----------------
__device__ float g_f1[NNODES * 256];   // layer-1 projected features
__device__ float g_h1[NNODES * 256];   // layer-1 output (post ELU)
__device__ float g_el1[NNODES * 8];
__device__ float g_er1[NNODES * 8];
__device__ float g_f2[NNODES * 32];    // layer-2 projected features
__device__ float g_el2[NNODES];
__device__ float g_er2[NNODES];
__device__ int   g_deg[NNODES];
__device__ int   g_off[NNODES + 1];
__device__ int   g_cur[NNODES];
__device__ int   g_elist[NEDGES];

// ---------------- CSR build ----------------
__global__ void k_zero_deg() {
    int i = blockIdx.x * blockDim.x + threadIdx.x;
    if (i < NNODES) g_deg[i] = 0;
}

__global__ void k_hist(const int* __restrict__ dst) {
    int e = blockIdx.x * blockDim.x + threadIdx.x;
    if (e < NEDGES) atomicAdd(&g_deg[dst[e]], 1);
}

// single-block scan over 50000 degrees
__global__ void k_scan() {
    __shared__ int partial[1024];
    const int T = 1024;
    const int chunk = (NNODES + T - 1) / T;  // 49
    int t = threadIdx.x;
    int s = 0;
    for (int i = 0; i < chunk; i++) {
        int idx = t * chunk + i;
        if (idx < NNODES) s += g_deg[idx];
    }
    partial[t] = s;
    __syncthreads();
    // Hillis-Steele inclusive scan
    for (int off = 1; off < T; off <<= 1) {
        int v = 0;
        if (t >= off) v = partial[t - off];
        __syncthreads();
        partial[t] += v;
        __syncthreads();
    }
    int base = partial[t] - s;  // exclusive prefix for this thread's chunk
    int run = base;
    for (int i = 0; i < chunk; i++) {
        int idx = t * chunk + i;
        if (idx < NNODES) {
            g_off[idx] = run;
            g_cur[idx] = run;
            run += g_deg[idx];
        }
    }
    if (t == T - 1) g_off[NNODES] = run;  // == NEDGES
}

__global__ void k_scatter(const int* __restrict__ dst) {
    int e = blockIdx.x * blockDim.x + threadIdx.x;
    if (e < NEDGES) {
        int p = atomicAdd(&g_cur[dst[e]], 1);
        g_elist[p] = e;
    }
}

// ---------------- tiled fp32 GEMM  C[M,NC] = A[M,K] * B[K,NC] ----------------
template <int BM, int BN, int BK, int TM, int TN, int K, int NC>
__global__ void sgemm(const float* __restrict__ A, const float* __restrict__ B,
                      float* __restrict__ C) {
    __shared__ float As[BK][BM];
    __shared__ float Bs[BK][BN];
    constexpr int TCOLS = BN / TN;
    constexpr int THREADS = (BM / TM) * (BN / TN);
    int tid = threadIdx.x;
    int tr = tid / TCOLS, tc = tid % TCOLS;
    int m0 = blockIdx.y * BM, n0 = blockIdx.x * BN;
    float acc[TM][TN];
#pragma unroll
    for (int i = 0; i < TM; i++)
#pragma unroll
        for (int j = 0; j < TN; j++) acc[i][j] = 0.f;

    for (int k0 = 0; k0 < K; k0 += BK) {
#pragma unroll
        for (int i = tid; i < BM * BK; i += THREADS) {
            int r = i / BK, c = i % BK;
            int m = m0 + r;
            As[c][r] = (m < NNODES) ? A[m * K + k0 + c] : 0.f;
        }
#pragma unroll
        for (int i = tid; i < BK * BN; i += THREADS) {
            int r = i / BN, c = i % BN;
            Bs[r][c] = B[(k0 + r) * NC + n0 + c];
        }
        __syncthreads();
#pragma unroll
        for (int k = 0; k < BK; k++) {
            float ar[TM], br[TN];
#pragma unroll
            for (int i = 0; i < TM; i += 4) {
                float4 v = *(const float4*)&As[k][tr * TM + i];
                ar[i] = v.x; ar[i + 1] = v.y; ar[i + 2] = v.z; ar[i + 3] = v.w;
            }
#pragma unroll
            for (int j = 0; j < TN; j += 4) {
                float4 v = *(const float4*)&Bs[k][tc * TN + j];
                br[j] = v.x; br[j + 1] = v.y; br[j + 2] = v.z; br[j + 3] = v.w;
            }
#pragma unroll
            for (int i = 0; i < TM; i++)
#pragma unroll
                for (int j = 0; j < TN; j++)
                    acc[i][j] = fmaf(ar[i], br[j], acc[i][j]);
        }
        __syncthreads();
    }
#pragma unroll
    for (int i = 0; i < TM; i++) {
        int m = m0 + tr * TM + i;
        if (m < NNODES) {
#pragma unroll
            for (int j = 0; j < TN; j++)
                C[m * NC + n0 + tc * TN + j] = acc[i][j];
        }
    }
}

// ---------------- attention logits ----------------
// layer 1: el[n,h] = sum_d f1[n, h*32+d] * al1[h*32+d]  (H=8, D=32)
__global__ void k_attn1(const float* __restrict__ al, const float* __restrict__ ar) {
    int t = blockIdx.x * blockDim.x + threadIdx.x;
    if (t >= NNODES * 8) return;
    int n = t >> 3, h = t & 7;
    const float4* f4 = (const float4*)(g_f1 + n * 256 + h * 32);
    const float4* a4 = (const float4*)(al + h * 32);
    const float4* r4 = (const float4*)(ar + h * 32);
    float sl = 0.f, sr = 0.f;
#pragma unroll
    for (int j = 0; j < 8; j++) {
        float4 v = f4[j], a = a4[j], b = r4[j];
        sl += v.x * a.x + v.y * a.y + v.z * a.z + v.w * a.w;
        sr += v.x * b.x + v.y * b.y + v.z * b.z + v.w * b.w;
    }
    g_el1[t] = sl;
    g_er1[t] = sr;
}

// layer 2: H=1, D=32
__global__ void k_attn2(const float* __restrict__ al, const float* __restrict__ ar) {
    int n = blockIdx.x * blockDim.x + threadIdx.x;
    if (n >= NNODES) return;
    const float4* f4 = (const float4*)(g_f2 + n * 32);
    const float4* a4 = (const float4*)al;
    const float4* r4 = (const float4*)ar;
    float sl = 0.f, sr = 0.f;
#pragma unroll
    for (int j = 0; j < 8; j++) {
        float4 v = f4[j], a = a4[j], b = r4[j];
        sl += v.x * a.x + v.y * a.y + v.z * a.z + v.w * a.w;
        sr += v.x * b.x + v.y * b.y + v.z * b.z + v.w * b.w;
    }
    g_el2[n] = sl;
    g_er2[n] = sr;
}

// ---------------- layer-1 GAT aggregation: warp per dst node ----------------
// out[n,h,:] = elu( (sum_e exp(lrelu(el[src]+er[n])) * f[src,h,:]) / (sum_e exp(...)) + b )
// No max-subtraction: logits are O(1) here, exp cannot overflow; mathematically identical.
__global__ void k_gat1(const int* __restrict__ srcArr, const float* __restrict__ bias) {
    int w = (blockIdx.x * blockDim.x + threadIdx.x) >> 5;
    if (w >= NNODES) return;
    int lane = threadIdx.x & 31;
    int beg = g_off[w], end = g_off[w + 1];
    float er_h = g_er1[w * 8 + (lane & 7)];
    int h0 = lane >> 3;        // head for float4 chunk 0 (dims 0..127)
    int h1 = 4 + (lane >> 3);  // head for float4 chunk 1 (dims 128..255)
    float denom = 0.f;
    float4 a0 = {0.f, 0.f, 0.f, 0.f};
    float4 a1 = {0.f, 0.f, 0.f, 0.f};
    const float4* f4 = (const float4*)g_f1;
    for (int i = beg; i < end; i++) {
        int e = g_elist[i];
        int s = srcArr[e];
        float ee = 0.f;
        if (lane < 8) {
            float v = g_el1[s * 8 + lane] + er_h;
            v = v > 0.f ? v : 0.2f * v;
            ee = __expf(v);
            denom += ee;
        }
        float c0 = __shfl_sync(0xffffffffu, ee, h0);
        float c1 = __shfl_sync(0xffffffffu, ee, h1);
        float4 v0 = f4[s * 64 + lane];
        float4 v1 = f4[s * 64 + 32 + lane];
        a0.x = fmaf(c0, v0.x, a0.x); a0.y = fmaf(c0, v0.y, a0.y);
        a0.z = fmaf(c0, v0.z, a0.z); a0.w = fmaf(c0, v0.w, a0.w);
        a1.x = fmaf(c1, v1.x, a1.x); a1.y = fmaf(c1, v1.y, a1.y);
        a1.z = fmaf(c1, v1.z, a1.z); a1.w = fmaf(c1, v1.w, a1.w);
    }
    float d0 = __shfl_sync(0xffffffffu, denom, h0);
    float d1 = __shfl_sync(0xffffffffu, denom, h1);
    if (end > beg) {
        float i0 = 1.f / d0, i1 = 1.f / d1;
        a0.x *= i0; a0.y *= i0; a0.z *= i0; a0.w *= i0;
        a1.x *= i1; a1.y *= i1; a1.z *= i1; a1.w *= i1;
    }
    float4 b0 = *(const float4*)(bias + lane * 4);
    float4 b1 = *(const float4*)(bias + 128 + lane * 4);
    a0.x += b0.x; a0.y += b0.y; a0.z += b0.z; a0.w += b0.w;
    a1.x += b1.x; a1.y += b1.y; a1.z += b1.z; a1.w += b1.w;
    // ELU
    a0.x = a0.x > 0.f ? a0.x : expm1f(a0.x);
    a0.y = a0.y > 0.f ? a0.y : expm1f(a0.y);
    a0.z = a0.z > 0.f ? a0.z : expm1f(a0.z);
    a0.w = a0.w > 0.f ? a0.w : expm1f(a0.w);
    a1.x = a1.x > 0.f ? a1.x : expm1f(a1.x);
    a1.y = a1.y > 0.f ? a1.y : expm1f(a1.y);
    a1.z = a1.z > 0.f ? a1.z : expm1f(a1.z);
    a1.w = a1.w > 0.f ? a1.w : expm1f(a1.w);
    ((float4*)g_h1)[w * 64 + lane] = a0;
    ((float4*)g_h1)[w * 64 + 32 + lane] = a1;
}

// ---------------- layer-2 GAT aggregation (H=1, D=32): warp per dst node ----------------
__global__ void k_gat2(const int* __restrict__ srcArr, const float* __restrict__ bias,
                       float* __restrict__ out) {
    int w = (blockIdx.x * blockDim.x + threadIdx.x) >> 5;
    if (w >= NNODES) return;
    int lane = threadIdx.x & 31;
    int beg = g_off[w], end = g_off[w + 1];
    float er = g_er2[w];
    float denom = 0.f, acc = 0.f;
    for (int i = beg; i < end; i++) {
        int e = g_elist[i];
        int s = srcArr[e];
        float v = g_el2[s] + er;
        v = v > 0.f ? v : 0.2f * v;
        float ee = __expf(v);
        denom += ee;
        acc = fmaf(ee, g_f2[s * 32 + lane], acc);
    }
    float r = (end > beg) ? acc / denom : 0.f;
    out[w * 32 + lane] = r + bias[lane];
}

// ---------------- host ----------------
extern "C" void kernel_launch(void* const* d_in, const int* in_sizes, int n_in,
                              void* d_out, int out_size) {
    const float* x   = (const float*)d_in[0];
    const int*   src = (const int*)d_in[1];
    const int*   dst = (const int*)d_in[2];
    const float* W1  = (const float*)d_in[3];
    const float* al1 = (const float*)d_in[4];
    const float* ar1 = (const float*)d_in[5];
    const float* b1  = (const float*)d_in[6];
    const float* W2  = (const float*)d_in[7];
    const float* al2 = (const float*)d_in[8];
    const float* ar2 = (const float*)d_in[9];
    const float* b2  = (const float*)d_in[10];
    float* out = (float*)d_out;

    void *pf1 = nullptr, *ph1 = nullptr, *pf2 = nullptr;
    cudaGetSymbolAddress(&pf1, g_f1);
    cudaGetSymbolAddress(&ph1, g_h1);
    cudaGetSymbolAddress(&pf2, g_f2);

    // CSR by destination (shared by both layers)
    k_zero_deg<<<(NNODES + 255) / 256, 256>>>();
    k_hist<<<(NEDGES + 255) / 256, 256>>>(dst);
    k_scan<<<1, 1024>>>();
    k_scatter<<<(NEDGES + 255) / 256, 256>>>(dst);

    // Layer 1
    sgemm<64, 64, 16, 4, 4, 128, 256>
        <<<dim3(256 / 64, (NNODES + 63) / 64), 256>>>(x, W1, (float*)pf1);
    k_attn1<<<(NNODES * 8 + 255) / 256, 256>>>(al1, ar1);
    k_gat1<<<(NNODES * 32 + 255) / 256, 256>>>(src, b1);

    // Layer 2
    sgemm<128, 32, 16, 4, 4, 256, 32>
        <<<dim3(1, (NNODES + 127) / 128), 256>>>((const float*)ph1, W2, (float*)pf2);
    k_attn2<<<(NNODES + 255) / 256, 256>>>(al2, ar2);
    k_gat2<<<(NNODES * 32 + 255) / 256, 256>>>(src, b2, out);
}

// round 2
// speedup vs baseline: 1.3272x; 1.3272x over previous
#include <cuda_runtime.h>
#include <math.h>

#define NNODES 50000
#define NEDGES 800000

// ---------------- static scratch ----------------
__device__ float g_f1[NNODES * 256];   // layer-1 projected features
__device__ float g_h1[NNODES * 256];   // layer-1 output (post ELU)
__device__ float g_el1[NNODES * 8];
__device__ float g_er1[NNODES * 8];
__device__ float g_f2[NNODES * 32];    // layer-2 projected features
__device__ float g_el2[NNODES];
__device__ float g_er2[NNODES];
__device__ int   g_deg[NNODES];
__device__ int   g_off[NNODES + 1];
__device__ int   g_cur[NNODES];
__device__ int   g_srclist[NEDGES];    // src node id per CSR slot (dst-grouped)

// ---------------- CSR build ----------------
__global__ void k_hist(const int* __restrict__ dst) {
    int e = blockIdx.x * blockDim.x + threadIdx.x;
    if (e < NEDGES) atomicAdd(&g_deg[dst[e]], 1);
}

__global__ void k_scan() {
    __shared__ int partial[1024];
    const int T = 1024;
    const int chunk = (NNODES + T - 1) / T;
    int t = threadIdx.x;
    int s = 0;
    for (int i = 0; i < chunk; i++) {
        int idx = t * chunk + i;
        if (idx < NNODES) s += g_deg[idx];
    }
    partial[t] = s;
    __syncthreads();
    for (int off = 1; off < T; off <<= 1) {
        int v = 0;
        if (t >= off) v = partial[t - off];
        __syncthreads();
        partial[t] += v;
        __syncthreads();
    }
    int run = partial[t] - s;
    for (int i = 0; i < chunk; i++) {
        int idx = t * chunk + i;
        if (idx < NNODES) {
            g_off[idx] = run;
            g_cur[idx] = run;
            run += g_deg[idx];
        }
    }
    if (t == T - 1) g_off[NNODES] = run;
}

__global__ void k_scatter(const int* __restrict__ src, const int* __restrict__ dst) {
    int e = blockIdx.x * blockDim.x + threadIdx.x;
    if (e < NEDGES) {
        int p = atomicAdd(&g_cur[dst[e]], 1);
        g_srclist[p] = src[e];
    }
}

// ---------------- tiled fp32 GEMM  C[M,NC] = A[M,K] * B[K,NC] ----------------
template <int BM, int BN, int BK, int TM, int TN, int K, int NC>
__global__ void __launch_bounds__((BM / TM) * (BN / TN))
sgemm(const float* __restrict__ A, const float* __restrict__ B, float* __restrict__ C) {
    __shared__ float As[BK][BM];
    __shared__ float Bs[BK][BN];
    constexpr int TCOLS = BN / TN;
    constexpr int THREADS = (BM / TM) * (BN / TN);
    constexpr int A4PR = BK / 4;   // float4s per A row
    constexpr int B4PR = BN / 4;   // float4s per B row
    int tid = threadIdx.x;
    int tr = tid / TCOLS, tc = tid % TCOLS;
    int m0 = blockIdx.y * BM, n0 = blockIdx.x * BN;
    float acc[TM][TN];
#pragma unroll
    for (int i = 0; i < TM; i++)
#pragma unroll
        for (int j = 0; j < TN; j++) acc[i][j] = 0.f;

    for (int k0 = 0; k0 < K; k0 += BK) {
        // load A tile (transposed into As[k][m])
#pragma unroll
        for (int idx = tid; idx < BM * A4PR; idx += THREADS) {
            int r = idx / A4PR, c4 = idx % A4PR;
            int m = m0 + r;
            float4 v = {0.f, 0.f, 0.f, 0.f};
            if (m < NNODES) v = *(const float4*)&A[m * K + k0 + c4 * 4];
            As[c4 * 4 + 0][r] = v.x;
            As[c4 * 4 + 1][r] = v.y;
            As[c4 * 4 + 2][r] = v.z;
            As[c4 * 4 + 3][r] = v.w;
        }
        // load B tile
#pragma unroll
        for (int idx = tid; idx < BK * B4PR; idx += THREADS) {
            int r = idx / B4PR, c4 = idx % B4PR;
            *(float4*)&Bs[r][c4 * 4] = *(const float4*)&B[(k0 + r) * NC + n0 + c4 * 4];
        }
        __syncthreads();
#pragma unroll
        for (int k = 0; k < BK; k++) {
            float ar[TM], br[TN];
#pragma unroll
            for (int i = 0; i < TM; i += 4) {
                float4 v = *(const float4*)&As[k][tr * TM + i];
                ar[i] = v.x; ar[i + 1] = v.y; ar[i + 2] = v.z; ar[i + 3] = v.w;
            }
#pragma unroll
            for (int j = 0; j < TN; j += 4) {
                float4 v = *(const float4*)&Bs[k][tc * TN + j];
                br[j] = v.x; br[j + 1] = v.y; br[j + 2] = v.z; br[j + 3] = v.w;
            }
#pragma unroll
            for (int i = 0; i < TM; i++)
#pragma unroll
                for (int j = 0; j < TN; j++)
                    acc[i][j] = fmaf(ar[i], br[j], acc[i][j]);
        }
        __syncthreads();
    }
#pragma unroll
    for (int i = 0; i < TM; i++) {
        int m = m0 + tr * TM + i;
        if (m < NNODES) {
#pragma unroll
            for (int j = 0; j < TN; j += 4) {
                float4 v = {acc[i][j], acc[i][j + 1], acc[i][j + 2], acc[i][j + 3]};
                *(float4*)&C[m * NC + n0 + tc * TN + j] = v;
            }
        }
    }
}

// ---------------- attention logits ----------------
__global__ void k_attn1(const float* __restrict__ al, const float* __restrict__ ar) {
    int t = blockIdx.x * blockDim.x + threadIdx.x;
    if (t >= NNODES * 8) return;
    int n = t >> 3, h = t & 7;
    const float4* f4 = (const float4*)(g_f1 + n * 256 + h * 32);
    const float4* a4 = (const float4*)(al + h * 32);
    const float4* r4 = (const float4*)(ar + h * 32);
    float sl = 0.f, sr = 0.f;
#pragma unroll
    for (int j = 0; j < 8; j++) {
        float4 v = f4[j], a = a4[j], b = r4[j];
        sl += v.x * a.x + v.y * a.y + v.z * a.z + v.w * a.w;
        sr += v.x * b.x + v.y * b.y + v.z * b.z + v.w * b.w;
    }
    g_el1[t] = sl;
    g_er1[t] = sr;
}

__global__ void k_attn2(const float* __restrict__ al, const float* __restrict__ ar) {
    int n = blockIdx.x * blockDim.x + threadIdx.x;
    if (n >= NNODES) return;
    const float4* f4 = (const float4*)(g_f2 + n * 32);
    const float4* a4 = (const float4*)al;
    const float4* r4 = (const float4*)ar;
    float sl = 0.f, sr = 0.f;
#pragma unroll
    for (int j = 0; j < 8; j++) {
        float4 v = f4[j], a = a4[j], b = r4[j];
        sl += v.x * a.x + v.y * a.y + v.z * a.z + v.w * a.w;
        sr += v.x * b.x + v.y * b.y + v.z * b.z + v.w * b.w;
    }
    g_el2[n] = sl;
    g_er2[n] = sr;
}

// ---------------- layer-1 GAT aggregation: warp per dst node ----------------
__global__ void k_gat1(const float* __restrict__ bias) {
    int w = (blockIdx.x * blockDim.x + threadIdx.x) >> 5;
    if (w >= NNODES) return;
    int lane = threadIdx.x & 31;
    int beg = g_off[w], end = g_off[w + 1];
    float er_h = g_er1[w * 8 + (lane & 7)];
    int h0 = lane >> 3;
    int h1 = 4 + (lane >> 3);
    float denom = 0.f;
    float4 a0 = {0.f, 0.f, 0.f, 0.f};
    float4 a1 = {0.f, 0.f, 0.f, 0.f};
    const float4* f4 = (const float4*)g_f1;

    int i = beg;
    for (; i + 4 <= end; i += 4) {
        int s0 = g_srclist[i], s1 = g_srclist[i + 1];
        int s2 = g_srclist[i + 2], s3 = g_srclist[i + 3];
        float l0 = 0.f, l1 = 0.f, l2 = 0.f, l3 = 0.f;
        if (lane < 8) {
            l0 = g_el1[s0 * 8 + lane]; l1 = g_el1[s1 * 8 + lane];
            l2 = g_el1[s2 * 8 + lane]; l3 = g_el1[s3 * 8 + lane];
        }
        float4 u0 = f4[s0 * 64 + lane],      w0 = f4[s0 * 64 + 32 + lane];
        float4 u1 = f4[s1 * 64 + lane],      w1 = f4[s1 * 64 + 32 + lane];
        float4 u2 = f4[s2 * 64 + lane],      w2 = f4[s2 * 64 + 32 + lane];
        float4 u3 = f4[s3 * 64 + lane],      w3 = f4[s3 * 64 + 32 + lane];
        float e0 = 0.f, e1 = 0.f, e2 = 0.f, e3 = 0.f;
        if (lane < 8) {
            float v;
            v = l0 + er_h; v = v > 0.f ? v : 0.2f * v; e0 = __expf(v);
            v = l1 + er_h; v = v > 0.f ? v : 0.2f * v; e1 = __expf(v);
            v = l2 + er_h; v = v > 0.f ? v : 0.2f * v; e2 = __expf(v);
            v = l3 + er_h; v = v > 0.f ? v : 0.2f * v; e3 = __expf(v);
            denom += e0 + e1 + e2 + e3;
        }
        float c;
        c = __shfl_sync(0xffffffffu, e0, h0);
        a0.x = fmaf(c, u0.x, a0.x); a0.y = fmaf(c, u0.y, a0.y);
        a0.z = fmaf(c, u0.z, a0.z); a0.w = fmaf(c, u0.w, a0.w);
        c = __shfl_sync(0xffffffffu, e0, h1);
        a1.x = fmaf(c, w0.x, a1.x); a1.y = fmaf(c, w0.y, a1.y);
        a1.z = fmaf(c, w0.z, a1.z); a1.w = fmaf(c, w0.w, a1.w);
        c = __shfl_sync(0xffffffffu, e1, h0);
        a0.x = fmaf(c, u1.x, a0.x); a0.y = fmaf(c, u1.y, a0.y);
        a0.z = fmaf(c, u1.z, a0.z); a0.w = fmaf(c, u1.w, a0.w);
        c = __shfl_sync(0xffffffffu, e1, h1);
        a1.x = fmaf(c, w1.x, a1.x); a1.y = fmaf(c, w1.y, a1.y);
        a1.z = fmaf(c, w1.z, a1.z); a1.w = fmaf(c, w1.w, a1.w);
        c = __shfl_sync(0xffffffffu, e2, h0);
        a0.x = fmaf(c, u2.x, a0.x); a0.y = fmaf(c, u2.y, a0.y);
        a0.z = fmaf(c, u2.z, a0.z); a0.w = fmaf(c, u2.w, a0.w);
        c = __shfl_sync(0xffffffffu, e2, h1);
        a1.x = fmaf(c, w2.x, a1.x); a1.y = fmaf(c, w2.y, a1.y);
        a1.z = fmaf(c, w2.z, a1.z); a1.w = fmaf(c, w2.w, a1.w);
        c = __shfl_sync(0xffffffffu, e3, h0);
        a0.x = fmaf(c, u3.x, a0.x); a0.y = fmaf(c, u3.y, a0.y);
        a0.z = fmaf(c, u3.z, a0.z); a0.w = fmaf(c, u3.w, a0.w);
        c = __shfl_sync(0xffffffffu, e3, h1);
        a1.x = fmaf(c, w3.x, a1.x); a1.y = fmaf(c, w3.y, a1.y);
        a1.z = fmaf(c, w3.z, a1.z); a1.w = fmaf(c, w3.w, a1.w);
    }
    for (; i < end; i++) {
        int s = g_srclist[i];
        float ee = 0.f;
        if (lane < 8) {
            float v = g_el1[s * 8 + lane] + er_h;
            v = v > 0.f ? v : 0.2f * v;
            ee = __expf(v);
            denom += ee;
        }
        float c0 = __shfl_sync(0xffffffffu, ee, h0);
        float c1 = __shfl_sync(0xffffffffu, ee, h1);
        float4 v0 = f4[s * 64 + lane];
        float4 v1 = f4[s * 64 + 32 + lane];
        a0.x = fmaf(c0, v0.x, a0.x); a0.y = fmaf(c0, v0.y, a0.y);
        a0.z = fmaf(c0, v0.z, a0.z); a0.w = fmaf(c0, v0.w, a0.w);
        a1.x = fmaf(c1, v1.x, a1.x); a1.y = fmaf(c1, v1.y, a1.y);
        a1.z = fmaf(c1, v1.z, a1.z); a1.w = fmaf(c1, v1.w, a1.w);
    }
    float d0 = __shfl_sync(0xffffffffu, denom, h0);
    float d1 = __shfl_sync(0xffffffffu, denom, h1);
    if (end > beg) {
        float i0 = 1.f / d0, i1 = 1.f / d1;
        a0.x *= i0; a0.y *= i0; a0.z *= i0; a0.w *= i0;
        a1.x *= i1; a1.y *= i1; a1.z *= i1; a1.w *= i1;
    }
    float4 b0 = *(const float4*)(bias + lane * 4);
    float4 b1 = *(const float4*)(bias + 128 + lane * 4);
    a0.x += b0.x; a0.y += b0.y; a0.z += b0.z; a0.w += b0.w;
    a1.x += b1.x; a1.y += b1.y; a1.z += b1.z; a1.w += b1.w;
    a0.x = a0.x > 0.f ? a0.x : expm1f(a0.x);
    a0.y = a0.y > 0.f ? a0.y : expm1f(a0.y);
    a0.z = a0.z > 0.f ? a0.z : expm1f(a0.z);
    a0.w = a0.w > 0.f ? a0.w : expm1f(a0.w);
    a1.x = a1.x > 0.f ? a1.x : expm1f(a1.x);
    a1.y = a1.y > 0.f ? a1.y : expm1f(a1.y);
    a1.z = a1.z > 0.f ? a1.z : expm1f(a1.z);
    a1.w = a1.w > 0.f ? a1.w : expm1f(a1.w);
    ((float4*)g_h1)[w * 64 + lane] = a0;
    ((float4*)g_h1)[w * 64 + 32 + lane] = a1;
}

// ---------------- layer-2 GAT aggregation (H=1, D=32) ----------------
__global__ void k_gat2(const float* __restrict__ bias, float* __restrict__ out) {
    int w = (blockIdx.x * blockDim.x + threadIdx.x) >> 5;
    if (w >= NNODES) return;
    int lane = threadIdx.x & 31;
    int beg = g_off[w], end = g_off[w + 1];
    float er = g_er2[w];
    float denom = 0.f, acc = 0.f;
    int i = beg;
    for (; i + 4 <= end; i += 4) {
        int s0 = g_srclist[i], s1 = g_srclist[i + 1];
        int s2 = g_srclist[i + 2], s3 = g_srclist[i + 3];
        float l0 = g_el2[s0], l1 = g_el2[s1], l2 = g_el2[s2], l3 = g_el2[s3];
        float f0 = g_f2[s0 * 32 + lane], f1v = g_f2[s1 * 32 + lane];
        float f2v = g_f2[s2 * 32 + lane], f3 = g_f2[s3 * 32 + lane];
        float v, e;
        v = l0 + er; v = v > 0.f ? v : 0.2f * v; e = __expf(v);
        denom += e; acc = fmaf(e, f0, acc);
        v = l1 + er; v = v > 0.f ? v : 0.2f * v; e = __expf(v);
        denom += e; acc = fmaf(e, f1v, acc);
        v = l2 + er; v = v > 0.f ? v : 0.2f * v; e = __expf(v);
        denom += e; acc = fmaf(e, f2v, acc);
        v = l3 + er; v = v > 0.f ? v : 0.2f * v; e = __expf(v);
        denom += e; acc = fmaf(e, f3, acc);
    }
    for (; i < end; i++) {
        int s = g_srclist[i];
        float v = g_el2[s] + er;
        v = v > 0.f ? v : 0.2f * v;
        float e = __expf(v);
        denom += e;
        acc = fmaf(e, g_f2[s * 32 + lane], acc);
    }
    float r = (end > beg) ? acc / denom : 0.f;
    out[w * 32 + lane] = r + bias[lane];
}

// ---------------- host ----------------
extern "C" void kernel_launch(void* const* d_in, const int* in_sizes, int n_in,
                              void* d_out, int out_size) {
    const float* x   = (const float*)d_in[0];
    const int*   src = (const int*)d_in[1];
    const int*   dst = (const int*)d_in[2];
    const float* W1  = (const float*)d_in[3];
    const float* al1 = (const float*)d_in[4];
    const float* ar1 = (const float*)d_in[5];
    const float* b1  = (const float*)d_in[6];
    const float* W2  = (const float*)d_in[7];
    const float* al2 = (const float*)d_in[8];
    const float* ar2 = (const float*)d_in[9];
    const float* b2  = (const float*)d_in[10];
    float* out = (float*)d_out;

    void *pf1 = nullptr, *ph1 = nullptr, *pf2 = nullptr, *pdeg = nullptr;
    cudaGetSymbolAddress(&pf1, g_f1);
    cudaGetSymbolAddress(&ph1, g_h1);
    cudaGetSymbolAddress(&pf2, g_f2);
    cudaGetSymbolAddress(&pdeg, g_deg);

    // CSR by destination (shared by both layers)
    cudaMemsetAsync(pdeg, 0, NNODES * sizeof(int));
    k_hist<<<(NEDGES + 255) / 256, 256>>>(dst);
    k_scan<<<1, 1024>>>();
    k_scatter<<<(NEDGES + 255) / 256, 256>>>(src, dst);

    // Layer 1
    sgemm<128, 128, 16, 8, 8, 128, 256>
        <<<dim3(256 / 128, (NNODES + 127) / 128), 256>>>(x, W1, (float*)pf1);
    k_attn1<<<(NNODES * 8 + 255) / 256, 256>>>(al1, ar1);
    k_gat1<<<(NNODES * 32 + 255) / 256, 256>>>(b1);

    // Layer 2
    sgemm<128, 32, 16, 4, 4, 256, 32>
        <<<dim3(1, (NNODES + 127) / 128), 256>>>((const float*)ph1, W2, (float*)pf2);
    k_attn2<<<(NNODES + 255) / 256, 256>>>(al2, ar2);
    k_gat2<<<(NNODES * 32 + 255) / 256, 256>>>(b2, out);
}

// round 7
// speedup vs baseline: 1.4391x; 1.0843x over previous
#include <cuda_runtime.h>
#include <cuda_bf16.h>
#include <math.h>
#include <stdint.h>

#define NNODES 50000
#define NEDGES 800000

// ---------------- static scratch ----------------
__device__ float g_f1[NNODES * 256];   // layer-1 projected features
__device__ float g_h1[NNODES * 256];   // layer-1 output (post ELU)
__device__ float g_el1[NNODES * 8];
__device__ float g_er1[NNODES * 8];
__device__ float g_f2[NNODES * 32];    // layer-2 projected features
__device__ float g_el2[NNODES];
__device__ float g_er2[NNODES];
__device__ int   g_deg[NNODES];
__device__ int   g_off[NNODES + 1];
__device__ int   g_cur[NNODES];
__device__ int   g_srclist[NEDGES];

// bf16 split operands for layer-1 GEMM
__device__ __nv_bfloat16 g_xh[NNODES * 128];
__device__ __nv_bfloat16 g_xl[NNODES * 128];
__device__ __nv_bfloat16 g_w1h[256 * 128];   // transposed: [n][k]
__device__ __nv_bfloat16 g_w1l[256 * 128];

// ---------------- CSR build ----------------
__global__ void k_hist(const int* __restrict__ dst) {
    int e = blockIdx.x * blockDim.x + threadIdx.x;
    if (e < NEDGES) atomicAdd(&g_deg[dst[e]], 1);
}

__global__ void k_scan() {
    __shared__ int partial[1024];
    const int T = 1024;
    const int chunk = (NNODES + T - 1) / T;
    int t = threadIdx.x;
    int s = 0;
    for (int i = 0; i < chunk; i++) {
        int idx = t * chunk + i;
        if (idx < NNODES) s += g_deg[idx];
    }
    partial[t] = s;
    __syncthreads();
    for (int off = 1; off < T; off <<= 1) {
        int v = 0;
        if (t >= off) v = partial[t - off];
        __syncthreads();
        partial[t] += v;
        __syncthreads();
    }
    int run = partial[t] - s;
    for (int i = 0; i < chunk; i++) {
        int idx = t * chunk + i;
        if (idx < NNODES) {
            g_off[idx] = run;
            g_cur[idx] = run;
            run += g_deg[idx];
        }
    }
    if (t == T - 1) g_off[NNODES] = run;
}

__global__ void k_scatter(const int* __restrict__ src, const int* __restrict__ dst) {
    int e = blockIdx.x * blockDim.x + threadIdx.x;
    if (e < NEDGES) {
        int p = atomicAdd(&g_cur[dst[e]], 1);
        g_srclist[p] = src[e];
    }
}

// ---------------- bf16 split conversions ----------------
__global__ void k_split_x(const float* __restrict__ x) {
    int i = blockIdx.x * blockDim.x + threadIdx.x;
    if (i >= NNODES * 128) return;
    float v = x[i];
    __nv_bfloat16 h = __float2bfloat16(v);
    g_xh[i] = h;
    g_xl[i] = __float2bfloat16(v - __bfloat162float(h));
}

__global__ void k_split_w1(const float* __restrict__ W) {
    int i = blockIdx.x * blockDim.x + threadIdx.x;
    if (i >= 128 * 256) return;
    int k = i >> 8, n = i & 255;       // W is [K=128][N=256]
    float v = W[i];
    __nv_bfloat16 h = __float2bfloat16(v);
    g_w1h[n * 128 + k] = h;
    g_w1l[n * 128 + k] = __float2bfloat16(v - __bfloat162float(h));
}

// ---------------- tensor-core GEMM1: C[50000,256] = X[.,128] @ W1 ----------------
// bf16 3-term split, mma.sync.m16n8k16, fp32 accumulate.
#define S_A 40  // smem row stride (bf16 units)

__device__ __forceinline__ void mma16816(float* c, const uint32_t* a, const uint32_t* b) {
    asm volatile(
        "mma.sync.aligned.m16n8k16.row.col.f32.bf16.bf16.f32 "
        "{%0,%1,%2,%3}, {%4,%5,%6,%7}, {%8,%9}, {%0,%1,%2,%3};"
        : "+f"(c[0]), "+f"(c[1]), "+f"(c[2]), "+f"(c[3])
        : "r"(a[0]), "r"(a[1]), "r"(a[2]), "r"(a[3]), "r"(b[0]), "r"(b[1]));
}

__global__ void __launch_bounds__(256) k_mma_gemm1(float* __restrict__ C) {
    __shared__ __nv_bfloat16 sAh[128 * S_A];
    __shared__ __nv_bfloat16 sAl[128 * S_A];
    __shared__ __nv_bfloat16 sBh[128 * S_A];
    __shared__ __nv_bfloat16 sBl[128 * S_A];
    int tid = threadIdx.x;
    int lane = tid & 31;
    int wid = tid >> 5;
    int wm = wid & 3;        // 4 warps along M (32 rows each)
    int wn = wid >> 2;       // 2 warps along N (64 cols each)
    int m_blk = blockIdx.y * 128;
    int n_blk = blockIdx.x * 128;
    int grp = lane >> 2;           // 0..7
    int qp = (lane & 3) * 2;       // 0,2,4,6

    float acc[2][8][4];
#pragma unroll
    for (int mt = 0; mt < 2; mt++)
#pragma unroll
        for (int nt = 0; nt < 8; nt++)
#pragma unroll
            for (int j = 0; j < 4; j++) acc[mt][nt][j] = 0.f;

    for (int k0 = 0; k0 < 128; k0 += 32) {
#pragma unroll
        for (int p = 0; p < 2; p++) {
            int idx = tid + p * 256;         // 0..511
            int r = idx >> 2;                // 0..127
            int c8 = (idx & 3) * 8;          // 0,8,16,24
            int m = m_blk + r;
            float4 vh = {0.f, 0.f, 0.f, 0.f}, vl = {0.f, 0.f, 0.f, 0.f};
            if (m < NNODES) {
                vh = *(const float4*)&g_xh[m * 128 + k0 + c8];
                vl = *(const float4*)&g_xl[m * 128 + k0 + c8];
            }
            *(float4*)&sAh[r * S_A + c8] = vh;
            *(float4*)&sAl[r * S_A + c8] = vl;
            int n = n_blk + r;
            *(float4*)&sBh[r * S_A + c8] = *(const float4*)&g_w1h[n * 128 + k0 + c8];
            *(float4*)&sBl[r * S_A + c8] = *(const float4*)&g_w1l[n * 128 + k0 + c8];
        }
        __syncthreads();
#pragma unroll
        for (int kk = 0; kk < 32; kk += 16) {
            uint32_t ah[2][4], al_[2][4];
#pragma unroll
            for (int mt = 0; mt < 2; mt++) {
                int r0 = (wm * 32 + mt * 16 + grp) * S_A + kk + qp;
                ah[mt][0] = *(const uint32_t*)&sAh[r0];
                ah[mt][1] = *(const uint32_t*)&sAh[r0 + 8 * S_A];
                ah[mt][2] = *(const uint32_t*)&sAh[r0 + 8];
                ah[mt][3] = *(const uint32_t*)&sAh[r0 + 8 * S_A + 8];
                al_[mt][0] = *(const uint32_t*)&sAl[r0];
                al_[mt][1] = *(const uint32_t*)&sAl[r0 + 8 * S_A];
                al_[mt][2] = *(const uint32_t*)&sAl[r0 + 8];
                al_[mt][3] = *(const uint32_t*)&sAl[r0 + 8 * S_A + 8];
            }
#pragma unroll
            for (int nt = 0; nt < 8; nt++) {
                int b0 = (wn * 64 + nt * 8 + grp) * S_A + kk + qp;
                uint32_t bh[2], bl[2];
                bh[0] = *(const uint32_t*)&sBh[b0];
                bh[1] = *(const uint32_t*)&sBh[b0 + 8];
                bl[0] = *(const uint32_t*)&sBl[b0];
                bl[1] = *(const uint32_t*)&sBl[b0 + 8];
#pragma unroll
                for (int mt = 0; mt < 2; mt++) {
                    mma16816(acc[mt][nt], ah[mt], bh);
                    mma16816(acc[mt][nt], ah[mt], bl);
                    mma16816(acc[mt][nt], al_[mt], bh);
                }
            }
        }
        __syncthreads();
    }
    // epilogue: c0,c1 -> (row, qp..qp+1); c2,c3 -> (row+8)
#pragma unroll
    for (int mt = 0; mt < 2; mt++) {
        int row = m_blk + wm * 32 + mt * 16 + grp;
#pragma unroll
        for (int nt = 0; nt < 8; nt++) {
            int col = n_blk + wn * 64 + nt * 8 + qp;
            if (row < NNODES) {
                float2 v0 = {acc[mt][nt][0], acc[mt][nt][1]};
                *(float2*)&C[row * 256 + col] = v0;
            }
            if (row + 8 < NNODES) {
                float2 v1 = {acc[mt][nt][2], acc[mt][nt][3]};
                *(float2*)&C[(row + 8) * 256 + col] = v1;
            }
        }
    }
}

// ---------------- tiled fp32 GEMM (layer 2) ----------------
template <int BM, int BN, int BK, int TM, int TN, int K, int NC>
__global__ void __launch_bounds__((BM / TM) * (BN / TN))
sgemm(const float* __restrict__ A, const float* __restrict__ B, float* __restrict__ C) {
    __shared__ float As[BK][BM];
    __shared__ float Bs[BK][BN];
    constexpr int TCOLS = BN / TN;
    constexpr int THREADS = (BM / TM) * (BN / TN);
    constexpr int A4PR = BK / 4;
    constexpr int B4PR = BN / 4;
    int tid = threadIdx.x;
    int tr = tid / TCOLS, tc = tid % TCOLS;
    int m0 = blockIdx.y * BM, n0 = blockIdx.x * BN;
    float acc[TM][TN];
#pragma unroll
    for (int i = 0; i < TM; i++)
#pragma unroll
        for (int j = 0; j < TN; j++) acc[i][j] = 0.f;

    for (int k0 = 0; k0 < K; k0 += BK) {
#pragma unroll
        for (int idx = tid; idx < BM * A4PR; idx += THREADS) {
            int r = idx / A4PR, c4 = idx % A4PR;
            int m = m0 + r;
            float4 v = {0.f, 0.f, 0.f, 0.f};
            if (m < NNODES) v = *(const float4*)&A[m * K + k0 + c4 * 4];
            As[c4 * 4 + 0][r] = v.x;
            As[c4 * 4 + 1][r] = v.y;
            As[c4 * 4 + 2][r] = v.z;
            As[c4 * 4 + 3][r] = v.w;
        }
#pragma unroll
        for (int idx = tid; idx < BK * B4PR; idx += THREADS) {
            int r = idx / B4PR, c4 = idx % B4PR;
            *(float4*)&Bs[r][c4 * 4] = *(const float4*)&B[(k0 + r) * NC + n0 + c4 * 4];
        }
        __syncthreads();
#pragma unroll
        for (int k = 0; k < BK; k++) {
            float ar[TM], br[TN];
#pragma unroll
            for (int i = 0; i < TM; i += 4) {
                float4 v = *(const float4*)&As[k][tr * TM + i];
                ar[i] = v.x; ar[i + 1] = v.y; ar[i + 2] = v.z; ar[i + 3] = v.w;
            }
#pragma unroll
            for (int j = 0; j < TN; j += 4) {
                float4 v = *(const float4*)&Bs[k][tc * TN + j];
                br[j] = v.x; br[j + 1] = v.y; br[j + 2] = v.z; br[j + 3] = v.w;
            }
#pragma unroll
            for (int i = 0; i < TM; i++)
#pragma unroll
                for (int j = 0; j < TN; j++)
                    acc[i][j] = fmaf(ar[i], br[j], acc[i][j]);
        }
        __syncthreads();
    }
#pragma unroll
    for (int i = 0; i < TM; i++) {
        int m = m0 + tr * TM + i;
        if (m < NNODES) {
#pragma unroll
            for (int j = 0; j < TN; j += 4) {
                float4 v = {acc[i][j], acc[i][j + 1], acc[i][j + 2], acc[i][j + 3]};
                *(float4*)&C[m * NC + n0 + tc * TN + j] = v;
            }
        }
    }
}

// ---------------- attention logits ----------------
__global__ void k_attn1(const float* __restrict__ al, const float* __restrict__ ar) {
    int t = blockIdx.x * blockDim.x + threadIdx.x;
    if (t >= NNODES * 8) return;
    int n = t >> 3, h = t & 7;
    const float4* f4 = (const float4*)(g_f1 + n * 256 + h * 32);
    const float4* a4 = (const float4*)(al + h * 32);
    const float4* r4 = (const float4*)(ar + h * 32);
    float sl = 0.f, sr = 0.f;
#pragma unroll
    for (int j = 0; j < 8; j++) {
        float4 v = f4[j], a = a4[j], b = r4[j];
        sl += v.x * a.x + v.y * a.y + v.z * a.z + v.w * a.w;
        sr += v.x * b.x + v.y * b.y + v.z * b.z + v.w * b.w;
    }
    g_el1[t] = sl;
    g_er1[t] = sr;
}

__global__ void k_attn2(const float* __restrict__ al, const float* __restrict__ ar) {
    int n = blockIdx.x * blockDim.x + threadIdx.x;
    if (n >= NNODES) return;
    const float4* f4 = (const float4*)(g_f2 + n * 32);
    const float4* a4 = (const float4*)al;
    const float4* r4 = (const float4*)ar;
    float sl = 0.f, sr = 0.f;
#pragma unroll
    for (int j = 0; j < 8; j++) {
        float4 v = f4[j], a = a4[j], b = r4[j];
        sl += v.x * a.x + v.y * a.y + v.z * a.z + v.w * a.w;
        sr += v.x * b.x + v.y * b.y + v.z * b.z + v.w * b.w;
    }
    g_el2[n] = sl;
    g_er2[n] = sr;
}

// ---------------- layer-1 GAT aggregation: warp per dst node ----------------
__global__ void k_gat1(const float* __restrict__ bias) {
    int w = (blockIdx.x * blockDim.x + threadIdx.x) >> 5;
    if (w >= NNODES) return;
    int lane = threadIdx.x & 31;
    int beg = g_off[w], end = g_off[w + 1];
    float er_h = g_er1[w * 8 + (lane & 7)];
    int h0 = lane >> 3;
    int h1 = 4 + (lane >> 3);
    float denom = 0.f;
    float4 a0 = {0.f, 0.f, 0.f, 0.f};
    float4 a1 = {0.f, 0.f, 0.f, 0.f};
    const float4* f4 = (const float4*)g_f1;

    int i = beg;
    for (; i + 4 <= end; i += 4) {
        int s0 = g_srclist[i], s1 = g_srclist[i + 1];
        int s2 = g_srclist[i + 2], s3 = g_srclist[i + 3];
        float l0 = 0.f, l1 = 0.f, l2 = 0.f, l3 = 0.f;
        if (lane < 8) {
            l0 = g_el1[s0 * 8 + lane]; l1 = g_el1[s1 * 8 + lane];
            l2 = g_el1[s2 * 8 + lane]; l3 = g_el1[s3 * 8 + lane];
        }
        float4 u0 = f4[s0 * 64 + lane],      w0 = f4[s0 * 64 + 32 + lane];
        float4 u1 = f4[s1 * 64 + lane],      w1 = f4[s1 * 64 + 32 + lane];
        float4 u2 = f4[s2 * 64 + lane],      w2 = f4[s2 * 64 + 32 + lane];
        float4 u3 = f4[s3 * 64 + lane],      w3 = f4[s3 * 64 + 32 + lane];
        float e0 = 0.f, e1 = 0.f, e2 = 0.f, e3 = 0.f;
        if (lane < 8) {
            float v;
            v = l0 + er_h; v = v > 0.f ? v : 0.2f * v; e0 = __expf(v);
            v = l1 + er_h; v = v > 0.f ? v : 0.2f * v; e1 = __expf(v);
            v = l2 + er_h; v = v > 0.f ? v : 0.2f * v; e2 = __expf(v);
            v = l3 + er_h; v = v > 0.f ? v : 0.2f * v; e3 = __expf(v);
            denom += e0 + e1 + e2 + e3;
        }
        float c;
        c = __shfl_sync(0xffffffffu, e0, h0);
        a0.x = fmaf(c, u0.x, a0.x); a0.y = fmaf(c, u0.y, a0.y);
        a0.z = fmaf(c, u0.z, a0.z); a0.w = fmaf(c, u0.w, a0.w);
        c = __shfl_sync(0xffffffffu, e0, h1);
        a1.x = fmaf(c, w0.x, a1.x); a1.y = fmaf(c, w0.y, a1.y);
        a1.z = fmaf(c, w0.z, a1.z); a1.w = fmaf(c, w0.w, a1.w);
        c = __shfl_sync(0xffffffffu, e1, h0);
        a0.x = fmaf(c, u1.x, a0.x); a0.y = fmaf(c, u1.y, a0.y);
        a0.z = fmaf(c, u1.z, a0.z); a0.w = fmaf(c, u1.w, a0.w);
        c = __shfl_sync(0xffffffffu, e1, h1);
        a1.x = fmaf(c, w1.x, a1.x); a1.y = fmaf(c, w1.y, a1.y);
        a1.z = fmaf(c, w1.z, a1.z); a1.w = fmaf(c, w1.w, a1.w);
        c = __shfl_sync(0xffffffffu, e2, h0);
        a0.x = fmaf(c, u2.x, a0.x); a0.y = fmaf(c, u2.y, a0.y);
        a0.z = fmaf(c, u2.z, a0.z); a0.w = fmaf(c, u2.w, a0.w);
        c = __shfl_sync(0xffffffffu, e2, h1);
        a1.x = fmaf(c, w2.x, a1.x); a1.y = fmaf(c, w2.y, a1.y);
        a1.z = fmaf(c, w2.z, a1.z); a1.w = fmaf(c, w2.w, a1.w);
        c = __shfl_sync(0xffffffffu, e3, h0);
        a0.x = fmaf(c, u3.x, a0.x); a0.y = fmaf(c, u3.y, a0.y);
        a0.z = fmaf(c, u3.z, a0.z); a0.w = fmaf(c, u3.w, a0.w);
        c = __shfl_sync(0xffffffffu, e3, h1);
        a1.x = fmaf(c, w3.x, a1.x); a1.y = fmaf(c, w3.y, a1.y);
        a1.z = fmaf(c, w3.z, a1.z); a1.w = fmaf(c, w3.w, a1.w);
    }
    for (; i < end; i++) {
        int s = g_srclist[i];
        float ee = 0.f;
        if (lane < 8) {
            float v = g_el1[s * 8 + lane] + er_h;
            v = v > 0.f ? v : 0.2f * v;
            ee = __expf(v);
            denom += ee;
        }
        float c0 = __shfl_sync(0xffffffffu, ee, h0);
        float c1 = __shfl_sync(0xffffffffu, ee, h1);
        float4 v0 = f4[s * 64 + lane];
        float4 v1 = f4[s * 64 + 32 + lane];
        a0.x = fmaf(c0, v0.x, a0.x); a0.y = fmaf(c0, v0.y, a0.y);
        a0.z = fmaf(c0, v0.z, a0.z); a0.w = fmaf(c0, v0.w, a0.w);
        a1.x = fmaf(c1, v1.x, a1.x); a1.y = fmaf(c1, v1.y, a1.y);
        a1.z = fmaf(c1, v1.z, a1.z); a1.w = fmaf(c1, v1.w, a1.w);
    }
    float d0 = __shfl_sync(0xffffffffu, denom, h0);
    float d1 = __shfl_sync(0xffffffffu, denom, h1);
    if (end > beg) {
        float i0 = 1.f / d0, i1 = 1.f / d1;
        a0.x *= i0; a0.y *= i0; a0.z *= i0; a0.w *= i0;
        a1.x *= i1; a1.y *= i1; a1.z *= i1; a1.w *= i1;
    }
    float4 b0 = *(const float4*)(bias + lane * 4);
    float4 b1 = *(const float4*)(bias + 128 + lane * 4);
    a0.x += b0.x; a0.y += b0.y; a0.z += b0.z; a0.w += b0.w;
    a1.x += b1.x; a1.y += b1.y; a1.z += b1.z; a1.w += b1.w;
    a0.x = a0.x > 0.f ? a0.x : expm1f(a0.x);
    a0.y = a0.y > 0.f ? a0.y : expm1f(a0.y);
    a0.z = a0.z > 0.f ? a0.z : expm1f(a0.z);
    a0.w = a0.w > 0.f ? a0.w : expm1f(a0.w);
    a1.x = a1.x > 0.f ? a1.x : expm1f(a1.x);
    a1.y = a1.y > 0.f ? a1.y : expm1f(a1.y);
    a1.z = a1.z > 0.f ? a1.z : expm1f(a1.z);
    a1.w = a1.w > 0.f ? a1.w : expm1f(a1.w);
    ((float4*)g_h1)[w * 64 + lane] = a0;
    ((float4*)g_h1)[w * 64 + 32 + lane] = a1;
}

// ---------------- layer-2 GAT aggregation (H=1, D=32) ----------------
__global__ void k_gat2(const float* __restrict__ bias, float* __restrict__ out) {
    int w = (blockIdx.x * blockDim.x + threadIdx.x) >> 5;
    if (w >= NNODES) return;
    int lane = threadIdx.x & 31;
    int beg = g_off[w], end = g_off[w + 1];
    float er = g_er2[w];
    float denom = 0.f, acc = 0.f;
    int i = beg;
    for (; i + 4 <= end; i += 4) {
        int s0 = g_srclist[i], s1 = g_srclist[i + 1];
        int s2 = g_srclist[i + 2], s3 = g_srclist[i + 3];
        float l0 = g_el2[s0], l1 = g_el2[s1], l2 = g_el2[s2], l3 = g_el2[s3];
        float f0 = g_f2[s0 * 32 + lane], f1v = g_f2[s1 * 32 + lane];
        float f2v = g_f2[s2 * 32 + lane], f3 = g_f2[s3 * 32 + lane];
        float v, e;
        v = l0 + er; v = v > 0.f ? v : 0.2f * v; e = __expf(v);
        denom += e; acc = fmaf(e, f0, acc);
        v = l1 + er; v = v > 0.f ? v : 0.2f * v; e = __expf(v);
        denom += e; acc = fmaf(e, f1v, acc);
        v = l2 + er; v = v > 0.f ? v : 0.2f * v; e = __expf(v);
        denom += e; acc = fmaf(e, f2v, acc);
        v = l3 + er; v = v > 0.f ? v : 0.2f * v; e = __expf(v);
        denom += e; acc = fmaf(e, f3, acc);
    }
    for (; i < end; i++) {
        int s = g_srclist[i];
        float v = g_el2[s] + er;
        v = v > 0.f ? v : 0.2f * v;
        float e = __expf(v);
        denom += e;
        acc = fmaf(e, g_f2[s * 32 + lane], acc);
    }
    float r = (end > beg) ? acc / denom : 0.f;
    out[w * 32 + lane] = r + bias[lane];
}

// ---------------- host ----------------
extern "C" void kernel_launch(void* const* d_in, const int* in_sizes, int n_in,
                              void* d_out, int out_size) {
    const float* x   = (const float*)d_in[0];
    const int*   src = (const int*)d_in[1];
    const int*   dst = (const int*)d_in[2];
    const float* W1  = (const float*)d_in[3];
    const float* al1 = (const float*)d_in[4];
    const float* ar1 = (const float*)d_in[5];
    const float* b1  = (const float*)d_in[6];
    const float* W2  = (const float*)d_in[7];
    const float* al2 = (const float*)d_in[8];
    const float* ar2 = (const float*)d_in[9];
    const float* b2  = (const float*)d_in[10];
    float* out = (float*)d_out;

    void *pf1 = nullptr, *ph1 = nullptr, *pf2 = nullptr, *pdeg = nullptr;
    cudaGetSymbolAddress(&pf1, g_f1);
    cudaGetSymbolAddress(&ph1, g_h1);
    cudaGetSymbolAddress(&pf2, g_f2);
    cudaGetSymbolAddress(&pdeg, g_deg);

    // CSR by destination (shared by both layers)
    cudaMemsetAsync(pdeg, 0, NNODES * sizeof(int));
    k_hist<<<(NEDGES + 255) / 256, 256>>>(dst);
    k_scan<<<1, 1024>>>();
    k_scatter<<<(NEDGES + 255) / 256, 256>>>(src, dst);

    // Layer 1: bf16-split tensor-core GEMM
    k_split_x<<<(NNODES * 128 + 255) / 256, 256>>>(x);
    k_split_w1<<<(128 * 256 + 255) / 256, 256>>>(W1);
    k_mma_gemm1<<<dim3(2, (NNODES + 127) / 128), 256>>>((float*)pf1);
    k_attn1<<<(NNODES * 8 + 255) / 256, 256>>>(al1, ar1);
    k_gat1<<<(NNODES * 32 + 255) / 256, 256>>>(b1);

    // Layer 2
    sgemm<128, 32, 16, 4, 4, 256, 32>
        <<<dim3(1, (NNODES + 127) / 128), 256>>>((const float*)ph1, W2, (float*)pf2);
    k_attn2<<<(NNODES + 255) / 256, 256>>>(al2, ar2);
    k_gat2<<<(NNODES * 32 + 255) / 256, 256>>>(b2, out);
}